// round 10
// baseline (speedup 1.0000x reference)
#include <cuda_runtime.h>
#include <cuda_bf16.h>
#include <cstdint>

#define FEAT_D 128
#define MAX_NODES 50176
#define MAX_EDGES 650240
#define TSTRIDE 72            // bf16 per smem row (144 B)
#define TILE_HALF (128 * TSTRIDE)          // bf16 elems per tensor-half
#define BUF_BF16  (4 * TILE_HALF)          // A_hi, A_lo, W_hi, W_lo
#define SMEM_BYTES (2 * BUF_BF16 * 2)      // double buffered: 147456 B

// ---- scratch (__device__ globals; no allocation allowed) ----
__device__ float g_h[MAX_NODES * FEAT_D];          // pooled features (fp32, for max)
__device__ __nv_bfloat16 g_fhi[MAX_NODES * FEAT_D];
__device__ __nv_bfloat16 g_flo[MAX_NODES * FEAT_D];
__device__ __nv_bfloat16 g_nhi[MAX_NODES * FEAT_D];
__device__ __nv_bfloat16 g_nlo[MAX_NODES * FEAT_D];
__device__ int   g_deg[MAX_NODES];
__device__ int   g_incl[MAX_NODES];
__device__ int   g_bsum[256];
__device__ int   g_bbase[256];
__device__ int   g_offs[MAX_NODES + 1];
__device__ int   g_cursor[MAX_NODES];
__device__ int2  g_rec[MAX_EDGES];
__device__ int   g_idx64;
// bf16 hi/lo weight images, row-major [128][K]: W_pool at 0 (K=128), W_neigh at 128*128 (K=256)
__device__ __nv_bfloat16 g_whi[128 * 384];
__device__ __nv_bfloat16 g_wlo[128 * 384];

// ============================ helpers ======================================
__device__ __forceinline__ uint32_t smem_to_u32(const void* p) {
    uint32_t a;
    asm("{ .reg .u64 t; cvta.to.shared.u64 t, %1; cvt.u32.u64 %0, t; }" : "=r"(a) : "l"(p));
    return a;
}
__device__ __forceinline__ uint32_t pack_bf2(__nv_bfloat162 v) {
    return ((uint32_t)__bfloat16_as_ushort(v.y) << 16) |
            (uint32_t)__bfloat16_as_ushort(v.x);
}
__device__ __forceinline__ void ldsm_x4(uint32_t* r, uint32_t addr) {
    asm volatile("ldmatrix.sync.aligned.m8n8.x4.shared.b16 {%0,%1,%2,%3}, [%4];"
        : "=r"(r[0]), "=r"(r[1]), "=r"(r[2]), "=r"(r[3]) : "r"(addr));
}
__device__ __forceinline__ void mma16816(float* c, const uint32_t* a, const uint32_t* b) {
    asm volatile("mma.sync.aligned.m16n8k16.row.col.f32.bf16.bf16.f32 "
        "{%0,%1,%2,%3}, {%4,%5,%6,%7}, {%8,%9}, {%0,%1,%2,%3};"
        : "+f"(c[0]), "+f"(c[1]), "+f"(c[2]), "+f"(c[3])
        : "r"(a[0]), "r"(a[1]), "r"(a[2]), "r"(a[3]), "r"(b[0]), "r"(b[1]));
}
__device__ __forceinline__ void cp_async16(uint32_t saddr, const void* gaddr) {
    asm volatile("cp.async.cg.shared.global [%0], [%1], 16;" :: "r"(saddr), "l"(gaddr));
}
#define CP_COMMIT() asm volatile("cp.async.commit_group;" ::: "memory")
#define CP_WAIT1()  asm volatile("cp.async.wait_group 1;" ::: "memory")
#define CP_WAIT0()  asm volatile("cp.async.wait_group 0;" ::: "memory")

// ============================ misc kernels =================================
// detect index dtype (block 0 / thread 0) + zero degree array (whole grid)
__global__ void detect_zero_kernel(const void* src, int E, int N) {
    int i = blockIdx.x * blockDim.x + threadIdx.x;
    if (i < N) g_deg[i] = 0;
    if (i == 0) {
        const long long* p = (const long long*)src;
        int n = E < 64 ? E : 64;
        int ok = 1;
        for (int j = 0; j < n; j++) {
            long long v = p[j];
            if (v < 0 || v >= (long long)N) { ok = 0; break; }
        }
        g_idx64 = ok;
    }
}
__device__ __forceinline__ int load_idx(const void* p, int i) {
    return g_idx64 ? (int)((const long long*)p)[i] : ((const int*)p)[i];
}
// load 4 consecutive indices e..e+3 (caller guarantees in range)
__device__ __forceinline__ void load_idx4(const void* p, int e, int* o) {
    if (g_idx64) {
        longlong2 a = ((const longlong2*)p)[(e >> 1) + 0];
        longlong2 b = ((const longlong2*)p)[(e >> 1) + 1];
        o[0] = (int)a.x; o[1] = (int)a.y; o[2] = (int)b.x; o[3] = (int)b.y;
    } else {
        int4 a = ((const int4*)p)[e >> 2];
        o[0] = a.x; o[1] = a.y; o[2] = a.z; o[3] = a.w;
    }
}

// Split W (row-major [128][K] fp32) into bf16 hi/lo row-major images.
__global__ void prep_w_kernel(const float* __restrict__ W, int K, int wofs) {
    int e = blockIdx.x * blockDim.x + threadIdx.x;
    if (e >= 128 * K) return;
    float v = W[e];
    __nv_bfloat16 h = __float2bfloat16(v);
    __nv_bfloat16 l = __float2bfloat16(v - __bfloat162float(h));
    g_whi[wofs + e] = h;
    g_wlo[wofs + e] = l;
}

// Split feat into bf16 hi/lo images; 2 x float4 per thread.
__global__ void prep_feat_kernel(const float* __restrict__ feat, int n4) {
    int i0 = (blockIdx.x * blockDim.x + threadIdx.x) * 2;
    #pragma unroll
    for (int t = 0; t < 2; t++) {
        int i = i0 + t;
        if (i >= n4) return;
        float4 v = ((const float4*)feat)[i];
        __nv_bfloat162 h0 = __float22bfloat162_rn(make_float2(v.x, v.y));
        __nv_bfloat162 h1 = __float22bfloat162_rn(make_float2(v.z, v.w));
        float2 f0 = __bfloat1622float2(h0), f1 = __bfloat1622float2(h1);
        __nv_bfloat162 l0 = __float22bfloat162_rn(make_float2(v.x - f0.x, v.y - f0.y));
        __nv_bfloat162 l1 = __float22bfloat162_rn(make_float2(v.z - f1.x, v.w - f1.y));
        ((uint2*)g_fhi)[i] = make_uint2(pack_bf2(h0), pack_bf2(h1));
        ((uint2*)g_flo)[i] = make_uint2(pack_bf2(l0), pack_bf2(l1));
    }
}

// ============================ CSR build ====================================
// 4 edges per thread, vectorized index loads.
__global__ void count_kernel(const void* __restrict__ dst, int E, int N) {
    int e0 = (blockIdx.x * blockDim.x + threadIdx.x) * 4;
    if (e0 >= E) return;
    if (e0 + 4 <= E) {
        int d[4];
        load_idx4(dst, e0, d);
        #pragma unroll
        for (int t = 0; t < 4; t++)
            if ((unsigned)d[t] < (unsigned)N) atomicAdd(&g_deg[d[t]], 1);
    } else {
        for (int e = e0; e < E; e++) {
            int d = load_idx(dst, e);
            if ((unsigned)d < (unsigned)N) atomicAdd(&g_deg[d], 1);
        }
    }
}
__global__ void scan1_kernel(int n) {
    __shared__ int s[512];
    int tid = threadIdx.x;
    int i = blockIdx.x * 512 + tid;
    int v = (i < n) ? g_deg[i] : 0;
    s[tid] = v;
    __syncthreads();
    #pragma unroll
    for (int off = 1; off < 512; off <<= 1) {
        int t = (tid >= off) ? s[tid - off] : 0;
        __syncthreads();
        s[tid] += t;
        __syncthreads();
    }
    if (i < n) g_incl[i] = s[tid];
    if (tid == 511) g_bsum[blockIdx.x] = s[511];
}
__global__ void scan2_kernel(int nblocks) {
    __shared__ int s[256];
    int tid = threadIdx.x;
    int v = (tid < nblocks) ? g_bsum[tid] : 0;
    s[tid] = v;
    __syncthreads();
    #pragma unroll
    for (int off = 1; off < 256; off <<= 1) {
        int t = (tid >= off) ? s[tid - off] : 0;
        __syncthreads();
        s[tid] += t;
        __syncthreads();
    }
    if (tid < nblocks) g_bbase[tid] = s[tid] - v;
}
__global__ void scan3_kernel(int n, int E) {
    int i = blockIdx.x * 512 + threadIdx.x;
    if (i >= n) return;
    int ex = g_incl[i] - g_deg[i] + g_bbase[blockIdx.x];
    g_offs[i]   = ex;
    g_cursor[i] = ex;
    if (i == n - 1) g_offs[n] = E;
}
__global__ void scatter_kernel(const float* __restrict__ weight,
                               const void* __restrict__ src,
                               const void* __restrict__ dst,
                               int E, int N) {
    int e0 = (blockIdx.x * blockDim.x + threadIdx.x) * 4;
    if (e0 >= E) return;
    if (e0 + 4 <= E) {
        int d[4], s[4];
        load_idx4(dst, e0, d);
        load_idx4(src, e0, s);
        float4 w = *(const float4*)(weight + e0);
        float wv[4] = {w.x, w.y, w.z, w.w};
        #pragma unroll
        for (int t = 0; t < 4; t++) {
            if ((unsigned)d[t] >= (unsigned)N || (unsigned)s[t] >= (unsigned)N) continue;
            int pos = atomicAdd(&g_cursor[d[t]], 1);
            g_rec[pos] = make_int2(s[t], __float_as_int(wv[t]));
        }
    } else {
        for (int e = e0; e < E; e++) {
            int d = load_idx(dst, e);
            int s = load_idx(src, e);
            if ((unsigned)d >= (unsigned)N || (unsigned)s >= (unsigned)N) continue;
            int pos = atomicAdd(&g_cursor[d], 1);
            g_rec[pos] = make_int2(s, __float_as_int(weight[e]));
        }
    }
}

// ============================ node max =====================================
// One warp per node; uniform unroll-8 groups with clamped edge index
// (max is idempotent, so re-processing the last edge is harmless).
__global__ void __launch_bounds__(256)
nodemax_kernel(int N) {
    int warp = (blockIdx.x * blockDim.x + threadIdx.x) >> 5;
    int lane = threadIdx.x & 31;
    if (warp >= N) return;

    int beg = g_offs[warp];
    int end = g_offs[warp + 1];

    float4 m;
    if (beg == end) {
        m = make_float4(0.f, 0.f, 0.f, 0.f);
    } else {
        const float NEG = -3.402823466e+38f;
        m = make_float4(NEG, NEG, NEG, NEG);
        const int last = end - 1;
        for (int e0 = beg; e0 < end; e0 += 8) {
            int2 r[8];
            #pragma unroll
            for (int t = 0; t < 8; t++) {
                int e = e0 + t; e = e < last ? e : last;
                r[t] = g_rec[e];
            }
            float4 v[8];
            #pragma unroll
            for (int t = 0; t < 8; t++)
                v[t] = *(const float4*)(g_h + (size_t)r[t].x * FEAT_D + lane * 4);
            #pragma unroll
            for (int t = 0; t < 8; t++) {
                float w = __int_as_float(r[t].y);
                m.x = fmaxf(m.x, v[t].x * w); m.y = fmaxf(m.y, v[t].y * w);
                m.z = fmaxf(m.z, v[t].z * w); m.w = fmaxf(m.w, v[t].w * w);
            }
        }
    }
    __nv_bfloat162 h0 = __float22bfloat162_rn(make_float2(m.x, m.y));
    __nv_bfloat162 h1 = __float22bfloat162_rn(make_float2(m.z, m.w));
    float2 f0 = __bfloat1622float2(h0), f1 = __bfloat1622float2(h1);
    __nv_bfloat162 l0 = __float22bfloat162_rn(make_float2(m.x - f0.x, m.y - f0.y));
    __nv_bfloat162 l1 = __float22bfloat162_rn(make_float2(m.z - f1.x, m.w - f1.y));
    int slot = warp * 32 + lane;
    ((uint2*)g_nhi)[slot] = make_uint2(pack_bf2(h0), pack_bf2(h1));
    ((uint2*)g_nlo)[slot] = make_uint2(pack_bf2(l0), pack_bf2(l1));
}

// ============================ mma.sync GEMM ================================
// C[M x 128] = A[M x K] @ W[128 x K]^T + bias, fp32 via bf16 hi/lo 3-MMA split.
// A/W pre-split bf16 in gmem. 128x128 CTA tile, K chunked by 64.
// 512 threads, 16 warps 4(M) x 4(N), warp tile 32x32. cp.async double buffer.
template <int K, bool CONCAT, bool WRITE_H>
__device__ __forceinline__ void load_chunk(int ch, int buf, int tid, int row0, int M,
                                           int wofs, uint32_t sU) {
    const __nv_bfloat16 *Ah, *Al;
    if (!CONCAT || ch < 2) { Ah = g_fhi; Al = g_flo; }
    else                   { Ah = g_nhi; Al = g_nlo; }
    const int k0  = (ch & 1) * 64;
    const int kw0 = ch * 64;
    uint32_t base = sU + (uint32_t)buf * (BUF_BF16 * 2);
    #pragma unroll
    for (int t = 0; t < 2; t++) {
        int idx = tid + t * 512;
        int row = idx >> 3;
        int seg = idx & 7;
        int gr = row0 + row; if (gr > M - 1) gr = M - 1;
        uint32_t d = base + (uint32_t)(row * (TSTRIDE * 2) + seg * 16);
        cp_async16(d,                     Ah + (size_t)gr * FEAT_D + k0 + seg * 8);
        cp_async16(d + 1 * TILE_HALF * 2, Al + (size_t)gr * FEAT_D + k0 + seg * 8);
        cp_async16(d + 2 * TILE_HALF * 2, g_whi + wofs + (size_t)row * K + kw0 + seg * 8);
        cp_async16(d + 3 * TILE_HALF * 2, g_wlo + wofs + (size_t)row * K + kw0 + seg * 8);
    }
}

template <int K, bool CONCAT, bool WRITE_H>
__global__ void __launch_bounds__(512)
gemm_mma_kernel(const float* __restrict__ bias, float* __restrict__ C, int M, int wofs)
{
    constexpr int NCHUNK = K / 64;
    extern __shared__ __nv_bfloat16 smem[];
    const uint32_t sU = smem_to_u32(smem);

    const int tid   = threadIdx.x;
    const int wid   = tid >> 5;
    const int lane  = tid & 31;
    const int row0  = blockIdx.x * 128;
    const int warpM = (wid >> 2) * 32;
    const int warpN = (wid & 3) * 32;

    float c[2][4][4];
    #pragma unroll
    for (int i = 0; i < 2; i++)
        #pragma unroll
        for (int j = 0; j < 4; j++)
            #pragma unroll
            for (int q = 0; q < 4; q++) c[i][j][q] = 0.f;

    const int a_row = (lane & 7) + ((lane >> 3) & 1) * 8;
    const int a_col = (lane >> 4) * 8;
    const int b_row = (lane & 7) + ((lane >> 4) & 1) * 8;
    const int b_col = ((lane >> 3) & 1) * 8;

    load_chunk<K, CONCAT, WRITE_H>(0, 0, tid, row0, M, wofs, sU);
    CP_COMMIT();

    for (int ch = 0; ch < NCHUNK; ch++) {
        if (ch + 1 < NCHUNK) {
            load_chunk<K, CONCAT, WRITE_H>(ch + 1, (ch + 1) & 1, tid, row0, M, wofs, sU);
            CP_COMMIT();
            CP_WAIT1();
        } else {
            CP_WAIT0();
        }
        __syncthreads();

        const uint32_t bb  = sU + (uint32_t)(ch & 1) * (BUF_BF16 * 2);
        const uint32_t uAh = bb;
        const uint32_t uAl = bb + 1 * TILE_HALF * 2;
        const uint32_t uWh = bb + 2 * TILE_HALF * 2;
        const uint32_t uWl = bb + 3 * TILE_HALF * 2;

        #pragma unroll
        for (int ks = 0; ks < 4; ks++) {
            const int k = ks * 16;
            uint32_t bh[2][4], bl[2][4];
            #pragma unroll
            for (int p = 0; p < 2; p++) {
                uint32_t boff = (uint32_t)((warpN + p * 16 + b_row) * TSTRIDE + k + b_col) * 2;
                ldsm_x4(bh[p], uWh + boff);
                ldsm_x4(bl[p], uWl + boff);
            }
            #pragma unroll
            for (int mf = 0; mf < 2; mf++) {
                uint32_t ah[4], al[4];
                uint32_t aoff = (uint32_t)((warpM + mf * 16 + a_row) * TSTRIDE + k + a_col) * 2;
                ldsm_x4(ah, uAh + aoff);
                ldsm_x4(al, uAl + aoff);
                #pragma unroll
                for (int nf = 0; nf < 4; nf++) {
                    const uint32_t* rbh = &bh[nf >> 1][(nf & 1) * 2];
                    const uint32_t* rbl = &bl[nf >> 1][(nf & 1) * 2];
                    mma16816(c[mf][nf], ah, rbh);
                    mma16816(c[mf][nf], ah, rbl);
                    mma16816(c[mf][nf], al, rbh);
                }
            }
        }
        if (ch + 1 < NCHUNK) __syncthreads();
    }

    // ---- epilogue ----
    #pragma unroll
    for (int mf = 0; mf < 2; mf++) {
        int r = row0 + warpM + mf * 16 + (lane >> 2);
        #pragma unroll
        for (int nf = 0; nf < 4; nf++) {
            int col = warpN + nf * 8 + 2 * (lane & 3);
            float b0 = bias[col], b1 = bias[col + 1];
            float* base = (WRITE_H ? g_h : C);
            if (r < M) {
                float2 o = make_float2(c[mf][nf][0] + b0, c[mf][nf][1] + b1);
                *(float2*)(base + (size_t)r * FEAT_D + col) = o;
            }
            if (r + 8 < M) {
                float2 o = make_float2(c[mf][nf][2] + b0, c[mf][nf][3] + b1);
                *(float2*)(base + (size_t)(r + 8) * FEAT_D + col) = o;
            }
        }
    }
}

// ---------------------------------------------------------------------------
extern "C" void kernel_launch(void* const* d_in, const int* in_sizes, int n_in,
                              void* d_out, int out_size)
{
    const float* feat    = (const float*)d_in[0];
    const float* weight  = (const float*)d_in[1];
    const void*  src     = d_in[2];
    const void*  dst     = d_in[3];
    const float* W_pool  = (const float*)d_in[4];
    const float* b_pool  = (const float*)d_in[5];
    const float* W_neigh = (const float*)d_in[6];
    const float* b_neigh = (const float*)d_in[7];
    float*       out     = (float*)d_out;

    const int N = in_sizes[0] / FEAT_D;   // 50000
    const int E = in_sizes[1];            // 640000

    const int gemm_blocks = (N + 127) / 128;
    const int scan_blocks = (N + 511) / 512;
    const int edge4_blocks = (E / 4 + 255) / 256 + 1;

    cudaFuncSetAttribute(gemm_mma_kernel<128, false, true>,
                         cudaFuncAttributeMaxDynamicSharedMemorySize, SMEM_BYTES);
    cudaFuncSetAttribute(gemm_mma_kernel<256, true, false>,
                         cudaFuncAttributeMaxDynamicSharedMemorySize, SMEM_BYTES);

    // 0) index dtype + zero degrees + pre-split weights and feat
    detect_zero_kernel<<<(N + 255) / 256, 256>>>(src, E, N);
    prep_w_kernel<<<(128 * 128 + 255) / 256, 256>>>(W_pool, 128, 0);
    prep_w_kernel<<<(128 * 256 + 255) / 256, 256>>>(W_neigh, 256, 128 * 128);
    prep_feat_kernel<<<(N * FEAT_D / 8 + 255) / 256, 256>>>(feat, N * FEAT_D / 4);

    // 1) h = feat @ W_pool^T + b_pool
    gemm_mma_kernel<128, false, true><<<gemm_blocks, 512, SMEM_BYTES>>>(
        b_pool, nullptr, N, 0);

    // 2) CSR build
    count_kernel<<<edge4_blocks, 256>>>(dst, E, N);
    scan1_kernel<<<scan_blocks, 512>>>(N);
    scan2_kernel<<<1, 256>>>(scan_blocks);
    scan3_kernel<<<scan_blocks, 512>>>(N, E);
    scatter_kernel<<<edge4_blocks, 256>>>(weight, src, dst, E, N);

    // 3) per-node register max -> bf16 hi/lo neigh images
    nodemax_kernel<<<(N * 32 + 255) / 256, 256>>>(N);

    // 4) out = concat(feat, neigh) @ W_neigh^T + b_neigh
    gemm_mma_kernel<256, true, false><<<gemm_blocks, 512, SMEM_BYTES>>>(
        b_neigh, out, N, 128 * 128);
}

// round 11
// speedup vs baseline: 1.0712x; 1.0712x over previous
#include <cuda_runtime.h>
#include <cuda_bf16.h>
#include <cstdint>

#define FEAT_D 128
#define MAX_NODES 50176
#define MAX_EDGES 650240
#define TSTRIDE 72            // bf16 per smem row (144 B)
#define TILE_HALF (128 * TSTRIDE)          // bf16 elems per tensor-half
#define BUF_BF16  (4 * TILE_HALF)          // A_hi, A_lo, W_hi, W_lo
#define SMEM_BYTES (2 * BUF_BF16 * 2)      // double buffered: 147456 B

// ---- scratch (__device__ globals; no allocation allowed) ----
__device__ float g_h[MAX_NODES * FEAT_D];          // pooled features (fp32, for max)
__device__ __nv_bfloat16 g_fhi[MAX_NODES * FEAT_D];
__device__ __nv_bfloat16 g_flo[MAX_NODES * FEAT_D];
__device__ __nv_bfloat16 g_nhi[MAX_NODES * FEAT_D];
__device__ __nv_bfloat16 g_nlo[MAX_NODES * FEAT_D];
__device__ int   g_deg[MAX_NODES];
__device__ int   g_incl[MAX_NODES];
__device__ int   g_bsum[256];
__device__ int   g_offs[MAX_NODES + 1];
__device__ int   g_cursor[MAX_NODES];
__device__ int2  g_rec[MAX_EDGES];
__device__ int   g_idx64;
// bf16 hi/lo weight images, row-major: W_pool elems [0,16384), W_neigh [16384,49152)
__device__ __nv_bfloat16 g_whi[128 * 384];
__device__ __nv_bfloat16 g_wlo[128 * 384];

// ============================ helpers ======================================
__device__ __forceinline__ uint32_t smem_to_u32(const void* p) {
    uint32_t a;
    asm("{ .reg .u64 t; cvta.to.shared.u64 t, %1; cvt.u32.u64 %0, t; }" : "=r"(a) : "l"(p));
    return a;
}
__device__ __forceinline__ uint32_t pack_bf2(__nv_bfloat162 v) {
    return ((uint32_t)__bfloat16_as_ushort(v.y) << 16) |
            (uint32_t)__bfloat16_as_ushort(v.x);
}
__device__ __forceinline__ void ldsm_x4(uint32_t* r, uint32_t addr) {
    asm volatile("ldmatrix.sync.aligned.m8n8.x4.shared.b16 {%0,%1,%2,%3}, [%4];"
        : "=r"(r[0]), "=r"(r[1]), "=r"(r[2]), "=r"(r[3]) : "r"(addr));
}
__device__ __forceinline__ void mma16816(float* c, const uint32_t* a, const uint32_t* b) {
    asm volatile("mma.sync.aligned.m16n8k16.row.col.f32.bf16.bf16.f32 "
        "{%0,%1,%2,%3}, {%4,%5,%6,%7}, {%8,%9}, {%0,%1,%2,%3};"
        : "+f"(c[0]), "+f"(c[1]), "+f"(c[2]), "+f"(c[3])
        : "r"(a[0]), "r"(a[1]), "r"(a[2]), "r"(a[3]), "r"(b[0]), "r"(b[1]));
}
__device__ __forceinline__ void cp_async16(uint32_t saddr, const void* gaddr) {
    asm volatile("cp.async.cg.shared.global [%0], [%1], 16;" :: "r"(saddr), "l"(gaddr));
}
#define CP_COMMIT() asm volatile("cp.async.commit_group;" ::: "memory")
#define CP_WAIT1()  asm volatile("cp.async.wait_group 1;" ::: "memory")
#define CP_WAIT0()  asm volatile("cp.async.wait_group 0;" ::: "memory")

__device__ __forceinline__ int load_idx(const void* p, int i) {
    return g_idx64 ? (int)((const long long*)p)[i] : ((const int*)p)[i];
}
__device__ __forceinline__ void load_idx4(const void* p, int e, int* o) {
    if (g_idx64) {
        longlong2 a = ((const longlong2*)p)[(e >> 1) + 0];
        longlong2 b = ((const longlong2*)p)[(e >> 1) + 1];
        o[0] = (int)a.x; o[1] = (int)a.y; o[2] = (int)b.x; o[3] = (int)b.y;
    } else {
        int4 a = ((const int4*)p)[e >> 2];
        o[0] = a.x; o[1] = a.y; o[2] = a.z; o[3] = a.w;
    }
}

// ============================ prep_all =====================================
// One launch: feat hi/lo split + W_pool/W_neigh hi/lo split + deg zero +
// parallel index-dtype detect. Block ranges: [0,F) feat, [F,F+WB) weights,
// [F+WB, F+WB+ZB) deg zero, last block = detect.
__global__ void prep_all_kernel(const float* __restrict__ feat,
                                const float* __restrict__ W_pool,
                                const float* __restrict__ W_neigh,
                                const void* __restrict__ src,
                                int n4, int F, int WB, int ZB, int E, int N)
{
    const int b   = blockIdx.x;
    const int tid = threadIdx.x;

    if (b < F) {                       // ---- feat split (1 float4/thread) ----
        int i = b * 256 + tid;
        if (i >= n4) return;
        float4 v = ((const float4*)feat)[i];
        __nv_bfloat162 h0 = __float22bfloat162_rn(make_float2(v.x, v.y));
        __nv_bfloat162 h1 = __float22bfloat162_rn(make_float2(v.z, v.w));
        float2 f0 = __bfloat1622float2(h0), f1 = __bfloat1622float2(h1);
        __nv_bfloat162 l0 = __float22bfloat162_rn(make_float2(v.x - f0.x, v.y - f0.y));
        __nv_bfloat162 l1 = __float22bfloat162_rn(make_float2(v.z - f1.x, v.w - f1.y));
        ((uint2*)g_fhi)[i] = make_uint2(pack_bf2(h0), pack_bf2(h1));
        ((uint2*)g_flo)[i] = make_uint2(pack_bf2(l0), pack_bf2(l1));
    } else if (b < F + WB) {           // ---- weight split ----
        int e = (b - F) * 256 + tid;
        if (e >= 128 * 384) return;
        float v = (e < 16384) ? W_pool[e] : W_neigh[e - 16384];
        __nv_bfloat16 h = __float2bfloat16(v);
        __nv_bfloat16 l = __float2bfloat16(v - __bfloat162float(h));
        g_whi[e] = h;
        g_wlo[e] = l;
    } else if (b < F + WB + ZB) {      // ---- zero degrees ----
        int i = (b - F - WB) * 256 + tid;
        if (i < N) g_deg[i] = 0;
    } else {                           // ---- parallel dtype detect ----
        __shared__ int ok;
        if (tid == 0) ok = 1;
        __syncthreads();
        int n = E < 64 ? E : 64;
        if (tid < n) {
            long long v = ((const long long*)src)[tid];
            if (v < 0 || v >= (long long)N) atomicExch(&ok, 0);
        }
        __syncthreads();
        if (tid == 0) g_idx64 = ok;
    }
}

// ============================ CSR build ====================================
__global__ void count_kernel(const void* __restrict__ dst, int E, int N) {
    int e0 = (blockIdx.x * blockDim.x + threadIdx.x) * 4;
    if (e0 >= E) return;
    if (e0 + 4 <= E) {
        int d[4];
        load_idx4(dst, e0, d);
        #pragma unroll
        for (int t = 0; t < 4; t++)
            if ((unsigned)d[t] < (unsigned)N) atomicAdd(&g_deg[d[t]], 1);
    } else {
        for (int e = e0; e < E; e++) {
            int d = load_idx(dst, e);
            if ((unsigned)d < (unsigned)N) atomicAdd(&g_deg[d], 1);
        }
    }
}
__global__ void scan1_kernel(int n) {
    __shared__ int s[512];
    int tid = threadIdx.x;
    int i = blockIdx.x * 512 + tid;
    int v = (i < n) ? g_deg[i] : 0;
    s[tid] = v;
    __syncthreads();
    #pragma unroll
    for (int off = 1; off < 512; off <<= 1) {
        int t = (tid >= off) ? s[tid - off] : 0;
        __syncthreads();
        s[tid] += t;
        __syncthreads();
    }
    if (i < n) g_incl[i] = s[tid];
    if (tid == 511) g_bsum[blockIdx.x] = s[511];
}
// scan3 folds the block-base prefix (<=512 block sums) into itself.
__global__ void scan3_kernel(int n, int E, int nblocks) {
    __shared__ int sb[512];
    int tid = threadIdx.x;
    int bid = blockIdx.x;
    sb[tid] = (tid < bid && tid < nblocks) ? g_bsum[tid] : 0;
    __syncthreads();
    #pragma unroll
    for (int off = 256; off > 0; off >>= 1) {
        if (tid < off) sb[tid] += sb[tid + off];
        __syncthreads();
    }
    int bbase = sb[0];
    int i = bid * 512 + tid;
    if (i >= n) return;
    int ex = g_incl[i] - g_deg[i] + bbase;
    g_offs[i]   = ex;
    g_cursor[i] = ex;
    if (i == n - 1) g_offs[n] = E;
}
__global__ void scatter_kernel(const float* __restrict__ weight,
                               const void* __restrict__ src,
                               const void* __restrict__ dst,
                               int E, int N) {
    int e0 = (blockIdx.x * blockDim.x + threadIdx.x) * 4;
    if (e0 >= E) return;
    if (e0 + 4 <= E) {
        int d[4], s[4];
        load_idx4(dst, e0, d);
        load_idx4(src, e0, s);
        float4 w = *(const float4*)(weight + e0);
        float wv[4] = {w.x, w.y, w.z, w.w};
        #pragma unroll
        for (int t = 0; t < 4; t++) {
            if ((unsigned)d[t] >= (unsigned)N || (unsigned)s[t] >= (unsigned)N) continue;
            int pos = atomicAdd(&g_cursor[d[t]], 1);
            g_rec[pos] = make_int2(s[t], __float_as_int(wv[t]));
        }
    } else {
        for (int e = e0; e < E; e++) {
            int d = load_idx(dst, e);
            int s = load_idx(src, e);
            if ((unsigned)d >= (unsigned)N || (unsigned)s >= (unsigned)N) continue;
            int pos = atomicAdd(&g_cursor[d], 1);
            g_rec[pos] = make_int2(s, __float_as_int(weight[e]));
        }
    }
}

// ============================ node max =====================================
__global__ void __launch_bounds__(256)
nodemax_kernel(int N) {
    int warp = (blockIdx.x * blockDim.x + threadIdx.x) >> 5;
    int lane = threadIdx.x & 31;
    if (warp >= N) return;

    int beg = g_offs[warp];
    int end = g_offs[warp + 1];

    float4 m;
    if (beg == end) {
        m = make_float4(0.f, 0.f, 0.f, 0.f);
    } else {
        const float NEG = -3.402823466e+38f;
        m = make_float4(NEG, NEG, NEG, NEG);
        const int last = end - 1;
        for (int e0 = beg; e0 < end; e0 += 8) {
            int2 r[8];
            #pragma unroll
            for (int t = 0; t < 8; t++) {
                int e = e0 + t; e = e < last ? e : last;
                r[t] = g_rec[e];
            }
            float4 v[8];
            #pragma unroll
            for (int t = 0; t < 8; t++)
                v[t] = *(const float4*)(g_h + (size_t)r[t].x * FEAT_D + lane * 4);
            #pragma unroll
            for (int t = 0; t < 8; t++) {
                float w = __int_as_float(r[t].y);
                m.x = fmaxf(m.x, v[t].x * w); m.y = fmaxf(m.y, v[t].y * w);
                m.z = fmaxf(m.z, v[t].z * w); m.w = fmaxf(m.w, v[t].w * w);
            }
        }
    }
    __nv_bfloat162 h0 = __float22bfloat162_rn(make_float2(m.x, m.y));
    __nv_bfloat162 h1 = __float22bfloat162_rn(make_float2(m.z, m.w));
    float2 f0 = __bfloat1622float2(h0), f1 = __bfloat1622float2(h1);
    __nv_bfloat162 l0 = __float22bfloat162_rn(make_float2(m.x - f0.x, m.y - f0.y));
    __nv_bfloat162 l1 = __float22bfloat162_rn(make_float2(m.z - f1.x, m.w - f1.y));
    int slot = warp * 32 + lane;
    ((uint2*)g_nhi)[slot] = make_uint2(pack_bf2(h0), pack_bf2(h1));
    ((uint2*)g_nlo)[slot] = make_uint2(pack_bf2(l0), pack_bf2(l1));
}

// ============================ mma.sync GEMM ================================
template <int K, bool CONCAT, bool WRITE_H>
__device__ __forceinline__ void load_chunk(int ch, int buf, int tid, int row0, int M,
                                           int wofs, uint32_t sU) {
    const __nv_bfloat16 *Ah, *Al;
    if (!CONCAT || ch < 2) { Ah = g_fhi; Al = g_flo; }
    else                   { Ah = g_nhi; Al = g_nlo; }
    const int k0  = (ch & 1) * 64;
    const int kw0 = ch * 64;
    uint32_t base = sU + (uint32_t)buf * (BUF_BF16 * 2);
    #pragma unroll
    for (int t = 0; t < 2; t++) {
        int idx = tid + t * 512;
        int row = idx >> 3;
        int seg = idx & 7;
        int gr = row0 + row; if (gr > M - 1) gr = M - 1;
        uint32_t d = base + (uint32_t)(row * (TSTRIDE * 2) + seg * 16);
        cp_async16(d,                     Ah + (size_t)gr * FEAT_D + k0 + seg * 8);
        cp_async16(d + 1 * TILE_HALF * 2, Al + (size_t)gr * FEAT_D + k0 + seg * 8);
        cp_async16(d + 2 * TILE_HALF * 2, g_whi + wofs + (size_t)row * K + kw0 + seg * 8);
        cp_async16(d + 3 * TILE_HALF * 2, g_wlo + wofs + (size_t)row * K + kw0 + seg * 8);
    }
}

template <int K, bool CONCAT, bool WRITE_H>
__global__ void __launch_bounds__(512)
gemm_mma_kernel(const float* __restrict__ bias, float* __restrict__ C, int M, int wofs)
{
    constexpr int NCHUNK = K / 64;
    extern __shared__ __nv_bfloat16 smem[];
    const uint32_t sU = smem_to_u32(smem);

    const int tid   = threadIdx.x;
    const int wid   = tid >> 5;
    const int lane  = tid & 31;
    const int row0  = blockIdx.x * 128;
    const int warpM = (wid >> 2) * 32;
    const int warpN = (wid & 3) * 32;

    float c[2][4][4];
    #pragma unroll
    for (int i = 0; i < 2; i++)
        #pragma unroll
        for (int j = 0; j < 4; j++)
            #pragma unroll
            for (int q = 0; q < 4; q++) c[i][j][q] = 0.f;

    const int a_row = (lane & 7) + ((lane >> 3) & 1) * 8;
    const int a_col = (lane >> 4) * 8;
    const int b_row = (lane & 7) + ((lane >> 4) & 1) * 8;
    const int b_col = ((lane >> 3) & 1) * 8;

    load_chunk<K, CONCAT, WRITE_H>(0, 0, tid, row0, M, wofs, sU);
    CP_COMMIT();

    for (int ch = 0; ch < NCHUNK; ch++) {
        if (ch + 1 < NCHUNK) {
            load_chunk<K, CONCAT, WRITE_H>(ch + 1, (ch + 1) & 1, tid, row0, M, wofs, sU);
            CP_COMMIT();
            CP_WAIT1();
        } else {
            CP_WAIT0();
        }
        __syncthreads();

        const uint32_t bb  = sU + (uint32_t)(ch & 1) * (BUF_BF16 * 2);
        const uint32_t uAh = bb;
        const uint32_t uAl = bb + 1 * TILE_HALF * 2;
        const uint32_t uWh = bb + 2 * TILE_HALF * 2;
        const uint32_t uWl = bb + 3 * TILE_HALF * 2;

        #pragma unroll
        for (int ks = 0; ks < 4; ks++) {
            const int k = ks * 16;
            uint32_t bh[2][4], bl[2][4];
            #pragma unroll
            for (int p = 0; p < 2; p++) {
                uint32_t boff = (uint32_t)((warpN + p * 16 + b_row) * TSTRIDE + k + b_col) * 2;
                ldsm_x4(bh[p], uWh + boff);
                ldsm_x4(bl[p], uWl + boff);
            }
            #pragma unroll
            for (int mf = 0; mf < 2; mf++) {
                uint32_t ah[4], al[4];
                uint32_t aoff = (uint32_t)((warpM + mf * 16 + a_row) * TSTRIDE + k + a_col) * 2;
                ldsm_x4(ah, uAh + aoff);
                ldsm_x4(al, uAl + aoff);
                #pragma unroll
                for (int nf = 0; nf < 4; nf++) {
                    const uint32_t* rbh = &bh[nf >> 1][(nf & 1) * 2];
                    const uint32_t* rbl = &bl[nf >> 1][(nf & 1) * 2];
                    mma16816(c[mf][nf], ah, rbh);
                    mma16816(c[mf][nf], ah, rbl);
                    mma16816(c[mf][nf], al, rbh);
                }
            }
        }
        if (ch + 1 < NCHUNK) __syncthreads();
    }

    // ---- epilogue ----
    #pragma unroll
    for (int mf = 0; mf < 2; mf++) {
        int r = row0 + warpM + mf * 16 + (lane >> 2);
        #pragma unroll
        for (int nf = 0; nf < 4; nf++) {
            int col = warpN + nf * 8 + 2 * (lane & 3);
            float b0 = bias[col], b1 = bias[col + 1];
            float* base = (WRITE_H ? g_h : C);
            if (r < M) {
                float2 o = make_float2(c[mf][nf][0] + b0, c[mf][nf][1] + b1);
                *(float2*)(base + (size_t)r * FEAT_D + col) = o;
            }
            if (r + 8 < M) {
                float2 o = make_float2(c[mf][nf][2] + b0, c[mf][nf][3] + b1);
                *(float2*)(base + (size_t)(r + 8) * FEAT_D + col) = o;
            }
        }
    }
}

// ---------------------------------------------------------------------------
extern "C" void kernel_launch(void* const* d_in, const int* in_sizes, int n_in,
                              void* d_out, int out_size)
{
    const float* feat    = (const float*)d_in[0];
    const float* weight  = (const float*)d_in[1];
    const void*  src     = d_in[2];
    const void*  dst     = d_in[3];
    const float* W_pool  = (const float*)d_in[4];
    const float* b_pool  = (const float*)d_in[5];
    const float* W_neigh = (const float*)d_in[6];
    const float* b_neigh = (const float*)d_in[7];
    float*       out     = (float*)d_out;

    const int N = in_sizes[0] / FEAT_D;   // 50000
    const int E = in_sizes[1];            // 640000

    const int gemm_blocks  = (N + 127) / 128;
    const int scan_blocks  = (N + 511) / 512;
    const int edge4_blocks = (E / 4 + 255) / 256 + 1;

    const int n4 = N * FEAT_D / 4;
    const int F  = (n4 + 255) / 256;
    const int WB = (128 * 384 + 255) / 256;
    const int ZB = (N + 255) / 256;

    cudaFuncSetAttribute(gemm_mma_kernel<128, false, true>,
                         cudaFuncAttributeMaxDynamicSharedMemorySize, SMEM_BYTES);
    cudaFuncSetAttribute(gemm_mma_kernel<256, true, false>,
                         cudaFuncAttributeMaxDynamicSharedMemorySize, SMEM_BYTES);

    // 0) fused prep: feat split + W splits + deg zero + parallel detect
    prep_all_kernel<<<F + WB + ZB + 1, 256>>>(feat, W_pool, W_neigh, src,
                                              n4, F, WB, ZB, E, N);

    // 1) h = feat @ W_pool^T + b_pool
    gemm_mma_kernel<128, false, true><<<gemm_blocks, 512, SMEM_BYTES>>>(
        b_pool, nullptr, N, 0);

    // 2) CSR build
    count_kernel<<<edge4_blocks, 256>>>(dst, E, N);
    scan1_kernel<<<scan_blocks, 512>>>(N);
    scan3_kernel<<<scan_blocks, 512>>>(N, E, scan_blocks);
    scatter_kernel<<<edge4_blocks, 256>>>(weight, src, dst, E, N);

    // 3) per-node register max -> bf16 hi/lo neigh images
    nodemax_kernel<<<(N * 32 + 255) / 256, 256>>>(N);

    // 4) out = concat(feat, neigh) @ W_neigh^T + b_neigh
    gemm_mma_kernel<256, true, false><<<gemm_blocks, 512, SMEM_BYTES>>>(
        b_neigh, out, N, 16384);
}

// round 12
// speedup vs baseline: 1.0720x; 1.0008x over previous
#include <cuda_runtime.h>
#include <cuda_bf16.h>
#include <cstdint>

#define FEAT_D 128
#define MAX_NODES 50176
#define MAX_EDGES 650240
#define TSTRIDE 72            // bf16 per smem row (144 B)
#define TILE_HALF (128 * TSTRIDE)          // bf16 elems per tensor-half
#define BUF_BF16  (4 * TILE_HALF)          // A_hi, A_lo, W_hi, W_lo
#define SMEM_BYTES (2 * BUF_BF16 * 2)      // double buffered: 147456 B

// ---- scratch (__device__ globals; no allocation allowed) ----
// INVARIANT: g_deg is all-zero on entry to kernel_launch (zero at module load;
// nodemax_kernel re-zeros it after use on every execution).
__device__ float g_h[MAX_NODES * FEAT_D];
__device__ __nv_bfloat16 g_fhi[MAX_NODES * FEAT_D];
__device__ __nv_bfloat16 g_flo[MAX_NODES * FEAT_D];
__device__ __nv_bfloat16 g_nhi[MAX_NODES * FEAT_D];
__device__ __nv_bfloat16 g_nlo[MAX_NODES * FEAT_D];
__device__ int   g_deg[MAX_NODES];
__device__ int   g_incl[MAX_NODES];
__device__ int   g_bsum[512];
__device__ int   g_offs[MAX_NODES + 1];
__device__ int   g_cursor[MAX_NODES];
__device__ int2  g_rec[MAX_EDGES];
__device__ int   g_idx64;
// bf16 hi/lo weight images, row-major: W_pool elems [0,16384), W_neigh [16384,49152)
__device__ __nv_bfloat16 g_whi[128 * 384];
__device__ __nv_bfloat16 g_wlo[128 * 384];

// ============================ helpers ======================================
__device__ __forceinline__ uint32_t smem_to_u32(const void* p) {
    uint32_t a;
    asm("{ .reg .u64 t; cvta.to.shared.u64 t, %1; cvt.u32.u64 %0, t; }" : "=r"(a) : "l"(p));
    return a;
}
__device__ __forceinline__ uint32_t pack_bf2(__nv_bfloat162 v) {
    return ((uint32_t)__bfloat16_as_ushort(v.y) << 16) |
            (uint32_t)__bfloat16_as_ushort(v.x);
}
__device__ __forceinline__ void ldsm_x4(uint32_t* r, uint32_t addr) {
    asm volatile("ldmatrix.sync.aligned.m8n8.x4.shared.b16 {%0,%1,%2,%3}, [%4];"
        : "=r"(r[0]), "=r"(r[1]), "=r"(r[2]), "=r"(r[3]) : "r"(addr));
}
__device__ __forceinline__ void mma16816(float* c, const uint32_t* a, const uint32_t* b) {
    asm volatile("mma.sync.aligned.m16n8k16.row.col.f32.bf16.bf16.f32 "
        "{%0,%1,%2,%3}, {%4,%5,%6,%7}, {%8,%9}, {%0,%1,%2,%3};"
        : "+f"(c[0]), "+f"(c[1]), "+f"(c[2]), "+f"(c[3])
        : "r"(a[0]), "r"(a[1]), "r"(a[2]), "r"(a[3]), "r"(b[0]), "r"(b[1]));
}
__device__ __forceinline__ void cp_async16(uint32_t saddr, const void* gaddr) {
    asm volatile("cp.async.cg.shared.global [%0], [%1], 16;" :: "r"(saddr), "l"(gaddr));
}
#define CP_COMMIT() asm volatile("cp.async.commit_group;" ::: "memory")
#define CP_WAIT1()  asm volatile("cp.async.wait_group 1;" ::: "memory")
#define CP_WAIT0()  asm volatile("cp.async.wait_group 0;" ::: "memory")

__device__ __forceinline__ int load_idx(const void* p, int i) {
    return g_idx64 ? (int)((const long long*)p)[i] : ((const int*)p)[i];
}
__device__ __forceinline__ void load_idx4_f(const void* p, int e, int* o, int i64) {
    if (i64) {
        longlong2 a = ((const longlong2*)p)[(e >> 1) + 0];
        longlong2 b = ((const longlong2*)p)[(e >> 1) + 1];
        o[0] = (int)a.x; o[1] = (int)a.y; o[2] = (int)b.x; o[3] = (int)b.y;
    } else {
        int4 a = ((const int4*)p)[e >> 2];
        o[0] = a.x; o[1] = a.y; o[2] = a.z; o[3] = a.w;
    }
}
__device__ __forceinline__ void load_idx4(const void* p, int e, int* o) {
    load_idx4_f(p, e, o, g_idx64);
}

// ============================ prep_all =====================================
// One launch: feat hi/lo split, W splits, AND edge-degree count (deg is
// guaranteed zero on entry). Count blocks detect index dtype inline.
__global__ void prep_all_kernel(const float* __restrict__ feat,
                                const float* __restrict__ W_pool,
                                const float* __restrict__ W_neigh,
                                const void* __restrict__ dst,
                                int n4, int F, int WB, int E, int N)
{
    const int b   = blockIdx.x;
    const int tid = threadIdx.x;

    if (b < F) {                       // ---- feat split (1 float4/thread) ----
        int i = b * 256 + tid;
        if (i >= n4) return;
        float4 v = ((const float4*)feat)[i];
        __nv_bfloat162 h0 = __float22bfloat162_rn(make_float2(v.x, v.y));
        __nv_bfloat162 h1 = __float22bfloat162_rn(make_float2(v.z, v.w));
        float2 f0 = __bfloat1622float2(h0), f1 = __bfloat1622float2(h1);
        __nv_bfloat162 l0 = __float22bfloat162_rn(make_float2(v.x - f0.x, v.y - f0.y));
        __nv_bfloat162 l1 = __float22bfloat162_rn(make_float2(v.z - f1.x, v.w - f1.y));
        ((uint2*)g_fhi)[i] = make_uint2(pack_bf2(h0), pack_bf2(h1));
        ((uint2*)g_flo)[i] = make_uint2(pack_bf2(l0), pack_bf2(l1));
    } else if (b < F + WB) {           // ---- weight split ----
        int e = (b - F) * 256 + tid;
        if (e >= 128 * 384) return;
        float v = (e < 16384) ? W_pool[e] : W_neigh[e - 16384];
        __nv_bfloat16 h = __float2bfloat16(v);
        __nv_bfloat16 l = __float2bfloat16(v - __bfloat162float(h));
        g_whi[e] = h;
        g_wlo[e] = l;
    } else {                           // ---- edge count (inline dtype detect) ----
        int cb = b - F - WB;
        // inline detect from first 4 int64 words (false-accept prob ~(1/N)^4)
        const long long* p64 = (const long long*)dst;
        int i64 = ((unsigned long long)p64[0] < (unsigned long long)N) &&
                  ((unsigned long long)p64[1] < (unsigned long long)N) &&
                  ((unsigned long long)p64[2] < (unsigned long long)N) &&
                  ((unsigned long long)p64[3] < (unsigned long long)N);
        if (cb == 0 && tid == 0) g_idx64 = i64;   // publish for later kernels
        int e0 = (cb * 256 + tid) * 4;
        if (e0 >= E) return;
        if (e0 + 4 <= E) {
            int d[4];
            load_idx4_f(dst, e0, d, i64);
            #pragma unroll
            for (int t = 0; t < 4; t++)
                if ((unsigned)d[t] < (unsigned)N) atomicAdd(&g_deg[d[t]], 1);
        } else {
            for (int e = e0; e < E; e++) {
                int d = i64 ? (int)((const long long*)dst)[e] : ((const int*)dst)[e];
                if ((unsigned)d < (unsigned)N) atomicAdd(&g_deg[d], 1);
            }
        }
    }
}

// ============================ scans ========================================
// shuffle-based per-block inclusive scan (512 threads, 2 barriers)
__global__ void scan1_kernel(int n) {
    __shared__ int swarp[16];
    int tid  = threadIdx.x;
    int lane = tid & 31;
    int widx = tid >> 5;
    int i = blockIdx.x * 512 + tid;
    int v = (i < n) ? g_deg[i] : 0;
    #pragma unroll
    for (int off = 1; off < 32; off <<= 1) {
        int t = __shfl_up_sync(0xffffffffu, v, off);
        if (lane >= off) v += t;
    }
    if (lane == 31) swarp[widx] = v;
    __syncthreads();
    if (widx == 0) {
        int w = (lane < 16) ? swarp[lane] : 0;
        #pragma unroll
        for (int off = 1; off < 16; off <<= 1) {
            int t = __shfl_up_sync(0xffffffffu, w, off);
            if (lane >= off) w += t;
        }
        if (lane < 16) swarp[lane] = w;
    }
    __syncthreads();
    if (widx > 0) v += swarp[widx - 1];
    if (i < n) g_incl[i] = v;
    if (tid == 511) g_bsum[blockIdx.x] = v;
}
// scan3 folds the block-base prefix into offsets + cursors.
__global__ void scan3_kernel(int n, int E, int nblocks) {
    __shared__ int sb[512];
    int tid = threadIdx.x;
    int bid = blockIdx.x;
    sb[tid] = (tid < bid && tid < nblocks) ? g_bsum[tid] : 0;
    __syncthreads();
    #pragma unroll
    for (int off = 256; off > 0; off >>= 1) {
        if (tid < off) sb[tid] += sb[tid + off];
        __syncthreads();
    }
    int bbase = sb[0];
    int i = bid * 512 + tid;
    if (i >= n) return;
    int ex = g_incl[i] - g_deg[i] + bbase;
    g_offs[i]   = ex;
    g_cursor[i] = ex;
    if (i == n - 1) g_offs[n] = E;
}
__global__ void scatter_kernel(const float* __restrict__ weight,
                               const void* __restrict__ src,
                               const void* __restrict__ dst,
                               int E, int N) {
    int e0 = (blockIdx.x * blockDim.x + threadIdx.x) * 4;
    if (e0 >= E) return;
    if (e0 + 4 <= E) {
        int d[4], s[4];
        load_idx4(dst, e0, d);
        load_idx4(src, e0, s);
        float4 w = *(const float4*)(weight + e0);
        float wv[4] = {w.x, w.y, w.z, w.w};
        #pragma unroll
        for (int t = 0; t < 4; t++) {
            if ((unsigned)d[t] >= (unsigned)N || (unsigned)s[t] >= (unsigned)N) continue;
            int pos = atomicAdd(&g_cursor[d[t]], 1);
            g_rec[pos] = make_int2(s[t], __float_as_int(wv[t]));
        }
    } else {
        for (int e = e0; e < E; e++) {
            int d = load_idx(dst, e);
            int s = load_idx(src, e);
            if ((unsigned)d >= (unsigned)N || (unsigned)s >= (unsigned)N) continue;
            int pos = atomicAdd(&g_cursor[d], 1);
            g_rec[pos] = make_int2(s, __float_as_int(weight[e]));
        }
    }
}

// ============================ node max =====================================
// One warp per node. Also re-zeros g_deg[node] to restore the entry invariant.
__global__ void __launch_bounds__(256)
nodemax_kernel(int N) {
    int warp = (blockIdx.x * blockDim.x + threadIdx.x) >> 5;
    int lane = threadIdx.x & 31;
    if (warp >= N) return;

    int beg = g_offs[warp];
    int end = g_offs[warp + 1];
    if (lane == 0) g_deg[warp] = 0;    // restore invariant for next execution

    float4 m;
    if (beg == end) {
        m = make_float4(0.f, 0.f, 0.f, 0.f);
    } else {
        const float NEG = -3.402823466e+38f;
        m = make_float4(NEG, NEG, NEG, NEG);
        const int last = end - 1;
        for (int e0 = beg; e0 < end; e0 += 8) {
            int2 r[8];
            #pragma unroll
            for (int t = 0; t < 8; t++) {
                int e = e0 + t; e = e < last ? e : last;
                r[t] = g_rec[e];
            }
            float4 v[8];
            #pragma unroll
            for (int t = 0; t < 8; t++)
                v[t] = *(const float4*)(g_h + (size_t)r[t].x * FEAT_D + lane * 4);
            #pragma unroll
            for (int t = 0; t < 8; t++) {
                float w = __int_as_float(r[t].y);
                m.x = fmaxf(m.x, v[t].x * w); m.y = fmaxf(m.y, v[t].y * w);
                m.z = fmaxf(m.z, v[t].z * w); m.w = fmaxf(m.w, v[t].w * w);
            }
        }
    }
    __nv_bfloat162 h0 = __float22bfloat162_rn(make_float2(m.x, m.y));
    __nv_bfloat162 h1 = __float22bfloat162_rn(make_float2(m.z, m.w));
    float2 f0 = __bfloat1622float2(h0), f1 = __bfloat1622float2(h1);
    __nv_bfloat162 l0 = __float22bfloat162_rn(make_float2(m.x - f0.x, m.y - f0.y));
    __nv_bfloat162 l1 = __float22bfloat162_rn(make_float2(m.z - f1.x, m.w - f1.y));
    int slot = warp * 32 + lane;
    ((uint2*)g_nhi)[slot] = make_uint2(pack_bf2(h0), pack_bf2(h1));
    ((uint2*)g_nlo)[slot] = make_uint2(pack_bf2(l0), pack_bf2(l1));
}

// ============================ mma.sync GEMM ================================
template <int K, bool CONCAT, bool WRITE_H>
__device__ __forceinline__ void load_chunk(int ch, int buf, int tid, int row0, int M,
                                           int wofs, uint32_t sU) {
    const __nv_bfloat16 *Ah, *Al;
    if (!CONCAT || ch < 2) { Ah = g_fhi; Al = g_flo; }
    else                   { Ah = g_nhi; Al = g_nlo; }
    const int k0  = (ch & 1) * 64;
    const int kw0 = ch * 64;
    uint32_t base = sU + (uint32_t)buf * (BUF_BF16 * 2);
    #pragma unroll
    for (int t = 0; t < 2; t++) {
        int idx = tid + t * 512;
        int row = idx >> 3;
        int seg = idx & 7;
        int gr = row0 + row; if (gr > M - 1) gr = M - 1;
        uint32_t d = base + (uint32_t)(row * (TSTRIDE * 2) + seg * 16);
        cp_async16(d,                     Ah + (size_t)gr * FEAT_D + k0 + seg * 8);
        cp_async16(d + 1 * TILE_HALF * 2, Al + (size_t)gr * FEAT_D + k0 + seg * 8);
        cp_async16(d + 2 * TILE_HALF * 2, g_whi + wofs + (size_t)row * K + kw0 + seg * 8);
        cp_async16(d + 3 * TILE_HALF * 2, g_wlo + wofs + (size_t)row * K + kw0 + seg * 8);
    }
}

template <int K, bool CONCAT, bool WRITE_H>
__global__ void __launch_bounds__(512)
gemm_mma_kernel(const float* __restrict__ bias, float* __restrict__ C, int M, int wofs)
{
    constexpr int NCHUNK = K / 64;
    extern __shared__ __nv_bfloat16 smem[];
    const uint32_t sU = smem_to_u32(smem);

    const int tid   = threadIdx.x;
    const int wid   = tid >> 5;
    const int lane  = tid & 31;
    const int row0  = blockIdx.x * 128;
    const int warpM = (wid >> 2) * 32;
    const int warpN = (wid & 3) * 32;

    float c[2][4][4];
    #pragma unroll
    for (int i = 0; i < 2; i++)
        #pragma unroll
        for (int j = 0; j < 4; j++)
            #pragma unroll
            for (int q = 0; q < 4; q++) c[i][j][q] = 0.f;

    const int a_row = (lane & 7) + ((lane >> 3) & 1) * 8;
    const int a_col = (lane >> 4) * 8;
    const int b_row = (lane & 7) + ((lane >> 4) & 1) * 8;
    const int b_col = ((lane >> 3) & 1) * 8;

    load_chunk<K, CONCAT, WRITE_H>(0, 0, tid, row0, M, wofs, sU);
    CP_COMMIT();

    for (int ch = 0; ch < NCHUNK; ch++) {
        if (ch + 1 < NCHUNK) {
            load_chunk<K, CONCAT, WRITE_H>(ch + 1, (ch + 1) & 1, tid, row0, M, wofs, sU);
            CP_COMMIT();
            CP_WAIT1();
        } else {
            CP_WAIT0();
        }
        __syncthreads();

        const uint32_t bb  = sU + (uint32_t)(ch & 1) * (BUF_BF16 * 2);
        const uint32_t uAh = bb;
        const uint32_t uAl = bb + 1 * TILE_HALF * 2;
        const uint32_t uWh = bb + 2 * TILE_HALF * 2;
        const uint32_t uWl = bb + 3 * TILE_HALF * 2;

        #pragma unroll
        for (int ks = 0; ks < 4; ks++) {
            const int k = ks * 16;
            uint32_t bh[2][4], bl[2][4];
            #pragma unroll
            for (int p = 0; p < 2; p++) {
                uint32_t boff = (uint32_t)((warpN + p * 16 + b_row) * TSTRIDE + k + b_col) * 2;
                ldsm_x4(bh[p], uWh + boff);
                ldsm_x4(bl[p], uWl + boff);
            }
            #pragma unroll
            for (int mf = 0; mf < 2; mf++) {
                uint32_t ah[4], al[4];
                uint32_t aoff = (uint32_t)((warpM + mf * 16 + a_row) * TSTRIDE + k + a_col) * 2;
                ldsm_x4(ah, uAh + aoff);
                ldsm_x4(al, uAl + aoff);
                #pragma unroll
                for (int nf = 0; nf < 4; nf++) {
                    const uint32_t* rbh = &bh[nf >> 1][(nf & 1) * 2];
                    const uint32_t* rbl = &bl[nf >> 1][(nf & 1) * 2];
                    mma16816(c[mf][nf], ah, rbh);
                    mma16816(c[mf][nf], ah, rbl);
                    mma16816(c[mf][nf], al, rbh);
                }
            }
        }
        if (ch + 1 < NCHUNK) __syncthreads();
    }

    // ---- epilogue ----
    #pragma unroll
    for (int mf = 0; mf < 2; mf++) {
        int r = row0 + warpM + mf * 16 + (lane >> 2);
        #pragma unroll
        for (int nf = 0; nf < 4; nf++) {
            int col = warpN + nf * 8 + 2 * (lane & 3);
            float b0 = bias[col], b1 = bias[col + 1];
            float* base = (WRITE_H ? g_h : C);
            if (r < M) {
                float2 o = make_float2(c[mf][nf][0] + b0, c[mf][nf][1] + b1);
                *(float2*)(base + (size_t)r * FEAT_D + col) = o;
            }
            if (r + 8 < M) {
                float2 o = make_float2(c[mf][nf][2] + b0, c[mf][nf][3] + b1);
                *(float2*)(base + (size_t)(r + 8) * FEAT_D + col) = o;
            }
        }
    }
}

// ---------------------------------------------------------------------------
extern "C" void kernel_launch(void* const* d_in, const int* in_sizes, int n_in,
                              void* d_out, int out_size)
{
    const float* feat    = (const float*)d_in[0];
    const float* weight  = (const float*)d_in[1];
    const void*  src     = d_in[2];
    const void*  dst     = d_in[3];
    const float* W_pool  = (const float*)d_in[4];
    const float* b_pool  = (const float*)d_in[5];
    const float* W_neigh = (const float*)d_in[6];
    const float* b_neigh = (const float*)d_in[7];
    float*       out     = (float*)d_out;

    const int N = in_sizes[0] / FEAT_D;   // 50000
    const int E = in_sizes[1];            // 640000

    const int gemm_blocks  = (N + 127) / 128;
    const int scan_blocks  = (N + 511) / 512;
    const int edge4_blocks = (E / 4 + 255) / 256 + 1;

    const int n4 = N * FEAT_D / 4;
    const int F  = (n4 + 255) / 256;
    const int WB = (128 * 384 + 255) / 256;
    const int CB = edge4_blocks;

    cudaFuncSetAttribute(gemm_mma_kernel<128, false, true>,
                         cudaFuncAttributeMaxDynamicSharedMemorySize, SMEM_BYTES);
    cudaFuncSetAttribute(gemm_mma_kernel<256, true, false>,
                         cudaFuncAttributeMaxDynamicSharedMemorySize, SMEM_BYTES);

    // 0) fused prep: feat split + W splits + edge-degree count (deg==0 invariant)
    prep_all_kernel<<<F + WB + CB, 256>>>(feat, W_pool, W_neigh, dst,
                                          n4, F, WB, E, N);

    // 1) h = feat @ W_pool^T + b_pool
    gemm_mma_kernel<128, false, true><<<gemm_blocks, 512, SMEM_BYTES>>>(
        b_pool, nullptr, N, 0);

    // 2) scan + scatter
    scan1_kernel<<<scan_blocks, 512>>>(N);
    scan3_kernel<<<scan_blocks, 512>>>(N, E, scan_blocks);
    scatter_kernel<<<edge4_blocks, 256>>>(weight, src, dst, E, N);

    // 3) per-node register max -> bf16 hi/lo neigh images (re-zeros g_deg)
    nodemax_kernel<<<(N * 32 + 255) / 256, 256>>>(N);

    // 4) out = concat(feat, neigh) @ W_neigh^T + b_neigh
    gemm_mma_kernel<256, true, false><<<gemm_blocks, 512, SMEM_BYTES>>>(
        b_neigh, out, N, 16384);
}